// round 2
// baseline (speedup 1.0000x reference)
#include <cuda_runtime.h>

// Problem constants
#define HH 8
#define NN 2048
#define ROWS (HH * NN)              // 16384
#define GAMMA 0.9f
#define TOL2 1e-12f                  // (1e-6)^2
#define MAX_ITER 50

// Launch shape: 128 co-resident blocks, 4096 warps, exactly 4 rows per warp.
#define NBLOCKS 128
#define NTHREADS 1024
#define NWARPS (NTHREADS / 32)
#define TOTAL_WARPS (NBLOCKS * NWARPS)   // 4096
#define RPW 4                             // rows per warp (consecutive, same head)

// Device-global scratch (no allocation allowed)
__device__ float    g_x[2][ROWS];        // ping-pong fixed-point iterate
__device__ float    g_bsum[2][NBLOCKS];  // per-block partial ||x - x_next||^2
__device__ unsigned g_arrive = 0;        // grid barrier arrival counter
__device__ unsigned g_gen    = 0;        // grid barrier generation (monotonic across replays)

// Software grid barrier: safe because all NBLOCKS blocks are co-resident.
__device__ __forceinline__ void grid_barrier() {
    __syncthreads();
    if (threadIdx.x == 0) {
        volatile unsigned* genp = &g_gen;
        unsigned my = *genp;             // read generation BEFORE arriving
        __threadfence();                 // make this block's prior writes visible
        unsigned prev = atomicAdd(&g_arrive, 1u);
        if (prev == NBLOCKS - 1) {
            atomicExch(&g_arrive, 0u);
            __threadfence();
            atomicAdd(&g_gen, 1u);       // release everyone
        } else {
            while (*genp == my) { }      // spin on L2-coherent volatile load
        }
        __threadfence();                 // acquire: see all other blocks' writes
    }
    __syncthreads();
}

extern __shared__ float s_dyn[];         // [ROWS] current x  +  [NWARPS] reduce scratch

__global__ void __launch_bounds__(NTHREADS, 1)
fp_kernel(const float* __restrict__ A, const float* __restrict__ b,
          float* __restrict__ out)
{
    float* xs  = s_dyn;                  // 16384 floats = current iterate x (all heads)
    float* red = s_dyn + ROWS;           // per-warp diff^2 partials
    __shared__ float parts[NBLOCKS];     // deterministic cross-block reduction scratch

    const int tid  = threadIdx.x;
    const int warp = tid >> 5;
    const int lane = tid & 31;
    const int gw   = blockIdx.x * NWARPS + warp;   // 0..4095
    const int r0   = gw * RPW;                      // first of 4 consecutive rows
    const int h    = r0 >> 11;                      // head (same for all 4 rows)

    // x0 = 0 (zero the smem copy; iteration 0 reads it)
    {
        float4 z4 = make_float4(0.f, 0.f, 0.f, 0.f);
        float4* xs4 = reinterpret_cast<float4*>(xs);
        for (int i = tid; i < ROWS / 4; i += NTHREADS) xs4[i] = z4;
    }
    __syncthreads();

    // Per-warp fixed pointers (A rows are contiguous: r0..r0+3)
    const float4* __restrict__ a4 =
        reinterpret_cast<const float4*>(A + (size_t)r0 * NN);
    const float4* __restrict__ x4base =
        reinterpret_cast<const float4*>(xs + h * NN);

    int finalbuf = 0;

    for (int iter = 0; iter <= MAX_ITER; ++iter) {
        const int par = iter & 1;
        float* __restrict__ xw = g_x[par];   // write buffer for x_{iter+1}

        // ---- batched matvec: 4 independent row-streams per warp ----
        float acc0 = 0.f, acc1 = 0.f, acc2 = 0.f, acc3 = 0.f;
        #pragma unroll
        for (int k = 0; k < 16; ++k) {
            const int off = lane + 32 * k;
            float4 xv = x4base[off];             // shared across all 4 rows (LDS)
            float4 a0 = a4[off];                 // 4 independent DRAM streams
            float4 a1 = a4[off + 512];           //  -> high MLP
            float4 a2 = a4[off + 1024];
            float4 a3 = a4[off + 1536];
            acc0 = fmaf(a0.x, xv.x, acc0);
            acc0 = fmaf(a0.y, xv.y, acc0);
            acc0 = fmaf(a0.z, xv.z, acc0);
            acc0 = fmaf(a0.w, xv.w, acc0);
            acc1 = fmaf(a1.x, xv.x, acc1);
            acc1 = fmaf(a1.y, xv.y, acc1);
            acc1 = fmaf(a1.z, xv.z, acc1);
            acc1 = fmaf(a1.w, xv.w, acc1);
            acc2 = fmaf(a2.x, xv.x, acc2);
            acc2 = fmaf(a2.y, xv.y, acc2);
            acc2 = fmaf(a2.z, xv.z, acc2);
            acc2 = fmaf(a2.w, xv.w, acc2);
            acc3 = fmaf(a3.x, xv.x, acc3);
            acc3 = fmaf(a3.y, xv.y, acc3);
            acc3 = fmaf(a3.z, xv.z, acc3);
            acc3 = fmaf(a3.w, xv.w, acc3);
        }
        #pragma unroll
        for (int o = 16; o > 0; o >>= 1) {
            acc0 += __shfl_xor_sync(0xFFFFFFFFu, acc0, o);
            acc1 += __shfl_xor_sync(0xFFFFFFFFu, acc1, o);
            acc2 += __shfl_xor_sync(0xFFFFFFFFu, acc2, o);
            acc3 += __shfl_xor_sync(0xFFFFFFFFu, acc3, o);
        }

        float lsum = 0.f;
        if (lane == 0) {
            float y0 = tanhf(GAMMA * acc0 + b[r0 + 0]);
            float y1 = tanhf(GAMMA * acc1 + b[r0 + 1]);
            float y2 = tanhf(GAMMA * acc2 + b[r0 + 2]);
            float y3 = tanhf(GAMMA * acc3 + b[r0 + 3]);
            xw[r0 + 0] = y0;
            xw[r0 + 1] = y1;
            xw[r0 + 2] = y2;
            xw[r0 + 3] = y3;
            float d0 = xs[r0 + 0] - y0;
            float d1 = xs[r0 + 1] - y1;
            float d2 = xs[r0 + 2] - y2;
            float d3 = xs[r0 + 3] - y3;
            lsum = d0 * d0 + d1 * d1 + d2 * d2 + d3 * d3;
        }

        // ---- block-level diff^2 reduction (deterministic order) ----
        if (lane == 0) red[warp] = lsum;
        __syncthreads();
        if (warp == 0) {
            float s = (lane < NWARPS) ? red[lane] : 0.f;
            #pragma unroll
            for (int o = 16; o > 0; o >>= 1)
                s += __shfl_xor_sync(0xFFFFFFFFu, s, o);
            if (lane == 0) g_bsum[par][blockIdx.x] = s;
        }

        grid_barrier();   // all x_{iter+1} writes + block sums now globally visible

        // ---- deterministic cross-block reduction (identical in every block) ----
        if (tid < NBLOCKS) parts[tid] = g_bsum[par][tid];
        __syncthreads();
        #pragma unroll
        for (int s = NBLOCKS / 2; s > 0; s >>= 1) {
            if (tid < s) parts[tid] += parts[tid + s];
            __syncthreads();
        }
        float sumsq = parts[0];
        __syncthreads();          // everyone done reading parts before reuse

        if (sumsq < TOL2 || iter == MAX_ITER) {
            // x_next just written IS tanh(g*A@z_star + b) = the answer.
            finalbuf = par;
            break;
        }

        // Reload the new iterate into shared memory for the next pass.
        {
            const float4* src = reinterpret_cast<const float4*>(g_x[par]);
            float4* dst = reinterpret_cast<float4*>(xs);
            for (int i = tid; i < ROWS / 4; i += NTHREADS) dst[i] = src[i];
        }
        __syncthreads();
    }

    // ---- copy final buffer to d_out (shape [8,2048] row-major == x layout) ----
    {
        const float4* src = reinterpret_cast<const float4*>(g_x[finalbuf]);
        float4* dst = reinterpret_cast<float4*>(out);
        for (int i = blockIdx.x * NTHREADS + tid; i < ROWS / 4; i += NBLOCKS * NTHREADS)
            dst[i] = src[i];
    }
}

extern "C" void kernel_launch(void* const* d_in, const int* in_sizes, int n_in,
                              void* d_out, int out_size)
{
    const float* A = (const float*)d_in[0];
    const float* b = (const float*)d_in[1];
    // Defensive: identify A by element count (A has 33.5M elems, b has 16384)
    if (n_in >= 2 && in_sizes[0] == ROWS) {
        A = (const float*)d_in[1];
        b = (const float*)d_in[0];
    }

    size_t smem = (size_t)ROWS * sizeof(float) + (size_t)NWARPS * sizeof(float);
    cudaFuncSetAttribute(fp_kernel, cudaFuncAttributeMaxDynamicSharedMemorySize,
                         (int)smem);
    fp_kernel<<<NBLOCKS, NTHREADS, smem>>>(A, b, (float*)d_out);
}

// round 3
// speedup vs baseline: 1.9492x; 1.9492x over previous
#include <cuda_runtime.h>
#include <cuda_fp16.h>

// Problem constants
#define HH 8
#define NN 2048
#define ROWS (HH * NN)               // 16384
#define GAMMA 0.9f
#define TOL2 1e-12f                  // (1e-6)^2
#define MAX_ITER 50

#define NBLOCKS 148
#define NTHREADS 1024
#define NWARPS (NTHREADS / 32)
#define NGROUPS (ROWS / 4)           // 4096 groups of 4 rows, one group per warp-pass

// Device-global scratch (no runtime allocation allowed)
__device__ __align__(16) __half g_Ah[(size_t)ROWS * NN];  // fp16 copy of A (67 MB, L2-resident)
__device__ float    g_x[2][ROWS];        // ping-pong fixed-point iterate
__device__ float    g_bsum[2][NBLOCKS];  // per-block partial ||x - x_next||^2
__device__ unsigned g_arrive = 0;        // grid barrier arrival counter
__device__ unsigned g_gen    = 0;        // grid barrier generation (monotonic across replays)

// Software grid barrier: safe because all NBLOCKS blocks are co-resident (1 per SM).
__device__ __forceinline__ void grid_barrier() {
    __syncthreads();
    if (threadIdx.x == 0) {
        volatile unsigned* genp = &g_gen;
        unsigned my = *genp;             // read generation BEFORE arriving
        __threadfence();                 // publish this block's prior writes
        unsigned prev = atomicAdd(&g_arrive, 1u);
        if (prev == NBLOCKS - 1) {
            atomicExch(&g_arrive, 0u);
            __threadfence();
            atomicAdd(&g_gen, 1u);       // release everyone
        } else {
            while (*genp == my) { }
        }
        __threadfence();                 // acquire
    }
    __syncthreads();
}

extern __shared__ float s_dyn[];         // [ROWS] current x  +  [NWARPS] reduce scratch

__global__ void __launch_bounds__(NTHREADS, 1)
fp_kernel(const float* __restrict__ A, const float* __restrict__ b,
          float* __restrict__ out)
{
    float* xs  = s_dyn;                  // 16384 floats: current iterate (all heads)
    float* red = s_dyn + ROWS;
    __shared__ float parts[256];

    const int tid  = threadIdx.x;
    const int warp = tid >> 5;
    const int lane = tid & 31;
    const int j    = lane & 7;           // lane within 8-lane row-group
    const int sub  = lane >> 3;          // which of the 4 rows this group-of-8 owns

    // Group assignment: round-robin over blocks so every SM gets 27-28 groups.
    const int gidx   = blockIdx.x + NBLOCKS * warp;
    const bool active = (gidx < NGROUPS);
    const int r0    = active ? gidx * 4 : 0;     // 4 consecutive rows, same head
    const int h     = r0 >> 11;
    const int myrow = r0 + sub;

    // x_0 = 0 in smem (also correct z_star if iter-0 "converged")
    {
        float4 z4 = make_float4(0.f, 0.f, 0.f, 0.f);
        float4* xs4 = reinterpret_cast<float4*>(xs);
        for (int i = tid; i < ROWS / 4; i += NTHREADS) xs4[i] = z4;
    }
    __syncthreads();

    const uint4*  a4 = reinterpret_cast<const uint4*>(g_Ah + (size_t)myrow * NN);
    const float4* x4 = reinterpret_cast<const float4*>(xs + h * NN);

    for (int k = 0; k < MAX_ITER; ++k) {
        const int par = k & 1;
        float lsum = 0.f;

        if (k == 0) {
            // ---- fused iter 0: convert A -> fp16 (lands hot in L2), x1 = tanh(b) ----
            const float4* Af4 = reinterpret_cast<const float4*>(A);
            uint4* Ah4 = reinterpret_cast<uint4*>(g_Ah);
            const size_t total8 = (size_t)ROWS * NN / 8;
            for (size_t i = (size_t)blockIdx.x * NTHREADS + tid; i < total8;
                 i += (size_t)NBLOCKS * NTHREADS) {
                float4 f0 = Af4[2 * i];
                float4 f1 = Af4[2 * i + 1];
                __half2 q0 = __floats2half2_rn(f0.x, f0.y);
                __half2 q1 = __floats2half2_rn(f0.z, f0.w);
                __half2 q2 = __floats2half2_rn(f1.x, f1.y);
                __half2 q3 = __floats2half2_rn(f1.z, f1.w);
                uint4 u;
                u.x = *reinterpret_cast<unsigned*>(&q0);
                u.y = *reinterpret_cast<unsigned*>(&q1);
                u.z = *reinterpret_cast<unsigned*>(&q2);
                u.w = *reinterpret_cast<unsigned*>(&q3);
                Ah4[i] = u;
            }
            int gi = blockIdx.x * NTHREADS + tid;
            if (gi < ROWS) {
                float y = tanhf(b[gi]);          // gamma*A@0 + b = b
                g_x[0][gi] = y;
                lsum = y * y;                    // diff vs x_0 = 0
            }
        } else if (active) {
            // ---- fp16 matvec: 4 rows per warp in one pass, 8 lanes per row ----
            float acc0 = 0.f, acc1 = 0.f;
            #pragma unroll 4
            for (int s = 0; s < 32; ++s) {
                uint4  av = a4[s * 8 + j];                  // 8 halfs of my row
                float4 xa = x4[s * 16 + 2 * j];
                float4 xb = x4[s * 16 + 2 * j + 1];
                __half2 h0 = *reinterpret_cast<__half2*>(&av.x);
                __half2 h1 = *reinterpret_cast<__half2*>(&av.y);
                __half2 h2 = *reinterpret_cast<__half2*>(&av.z);
                __half2 h3 = *reinterpret_cast<__half2*>(&av.w);
                float2 f0 = __half22float2(h0);
                float2 f1 = __half22float2(h1);
                float2 f2 = __half22float2(h2);
                float2 f3 = __half22float2(h3);
                acc0 = fmaf(f0.x, xa.x, acc0);
                acc0 = fmaf(f0.y, xa.y, acc0);
                acc0 = fmaf(f1.x, xa.z, acc0);
                acc0 = fmaf(f1.y, xa.w, acc0);
                acc1 = fmaf(f2.x, xb.x, acc1);
                acc1 = fmaf(f2.y, xb.y, acc1);
                acc1 = fmaf(f3.x, xb.z, acc1);
                acc1 = fmaf(f3.y, xb.w, acc1);
            }
            float acc = acc0 + acc1;
            acc += __shfl_xor_sync(0xFFFFFFFFu, acc, 1);
            acc += __shfl_xor_sync(0xFFFFFFFFu, acc, 2);
            acc += __shfl_xor_sync(0xFFFFFFFFu, acc, 4);
            if (j == 0) {
                float y = tanhf(GAMMA * acc + b[myrow]);
                g_x[par][myrow] = y;
                float d = xs[myrow] - y;
                lsum = d * d;
            }
        }

        // ---- deterministic block reduction of lsum ----
        #pragma unroll
        for (int o = 16; o > 0; o >>= 1)
            lsum += __shfl_xor_sync(0xFFFFFFFFu, lsum, o);
        if (lane == 0) red[warp] = lsum;
        __syncthreads();
        if (warp == 0) {
            float s = (lane < NWARPS) ? red[lane] : 0.f;
            #pragma unroll
            for (int o = 16; o > 0; o >>= 1)
                s += __shfl_xor_sync(0xFFFFFFFFu, s, o);
            if (lane == 0) g_bsum[par][blockIdx.x] = s;
        }

        grid_barrier();   // publish x_{k+1} + block sums

        // ---- deterministic cross-block reduction (identical in every block) ----
        if (tid < 256) parts[tid] = (tid < NBLOCKS) ? g_bsum[par][tid] : 0.f;
        __syncthreads();
        #pragma unroll
        for (int s = 128; s > 0; s >>= 1) {
            if (tid < s) parts[tid] += parts[tid + s];
            __syncthreads();
        }
        float sumsq = parts[0];
        __syncthreads();

        if (sumsq < TOL2) break;     // xs still holds z_star = x_k

        // accept x_{k+1}: reload smem iterate
        {
            const float4* src = reinterpret_cast<const float4*>(g_x[par]);
            float4* dst = reinterpret_cast<float4*>(xs);
            for (int i = tid; i < ROWS / 4; i += NTHREADS) dst[i] = src[i];
        }
        __syncthreads();
    }
    // Here xs = z_star (x_k on break, x_50 if loop exhausted — matches torch loop).

    // ---- final differentiable step with ORIGINAL fp32 A: out = tanh(g*A@z_star + b) ----
    if (active) {
        const float4* A4 = reinterpret_cast<const float4*>(A + (size_t)myrow * NN);
        float acc0 = 0.f, acc1 = 0.f;
        #pragma unroll 4
        for (int s = 0; s < 32; ++s) {
            float4 aa = A4[s * 16 + 2 * j];
            float4 ab = A4[s * 16 + 2 * j + 1];
            float4 xa = x4[s * 16 + 2 * j];
            float4 xb = x4[s * 16 + 2 * j + 1];
            acc0 = fmaf(aa.x, xa.x, acc0);
            acc0 = fmaf(aa.y, xa.y, acc0);
            acc0 = fmaf(aa.z, xa.z, acc0);
            acc0 = fmaf(aa.w, xa.w, acc0);
            acc1 = fmaf(ab.x, xb.x, acc1);
            acc1 = fmaf(ab.y, xb.y, acc1);
            acc1 = fmaf(ab.z, xb.z, acc1);
            acc1 = fmaf(ab.w, xb.w, acc1);
        }
        float acc = acc0 + acc1;
        acc += __shfl_xor_sync(0xFFFFFFFFu, acc, 1);
        acc += __shfl_xor_sync(0xFFFFFFFFu, acc, 2);
        acc += __shfl_xor_sync(0xFFFFFFFFu, acc, 4);
        if (j == 0)
            out[myrow] = tanhf(GAMMA * acc + b[myrow]);
    }
}

extern "C" void kernel_launch(void* const* d_in, const int* in_sizes, int n_in,
                              void* d_out, int out_size)
{
    const float* A = (const float*)d_in[0];
    const float* b = (const float*)d_in[1];
    if (n_in >= 2 && in_sizes[0] == ROWS) {   // defensive: A is the 33.5M-elem input
        A = (const float*)d_in[1];
        b = (const float*)d_in[0];
    }

    size_t smem = (size_t)ROWS * sizeof(float) + (size_t)NWARPS * sizeof(float);
    cudaFuncSetAttribute(fp_kernel, cudaFuncAttributeMaxDynamicSharedMemorySize,
                         (int)smem);
    fp_kernel<<<NBLOCKS, NTHREADS, smem>>>(A, b, (float*)d_out);
}

// round 4
// speedup vs baseline: 3.1079x; 1.5944x over previous
#include <cuda_runtime.h>
#include <cuda_fp16.h>

// Problem constants
#define HH 8
#define NN 2048
#define ROWS (HH * NN)               // 16384
#define GAMMA 0.9f
#define TOL2 1e-12f                  // (1e-6)^2
#define MAX_ITER 50

#define NBLOCKS 128                  // 128 rows per block, 16 blocks per head
#define NTHREADS 1024
#define NWARPS 32
#define RB_TILES (ROWS / 16)         // 1024 row-tiles of 16
#define KB_TILES (NN / 16)           // 128  k-tiles of 16
#define NFRAG ((size_t)RB_TILES * KB_TILES * 32)   // uint4 fragments

// Device-global scratch (no runtime allocation allowed)
__device__ __align__(16) uint4 g_Ahf[NFRAG];   // fp16 A in mma-fragment layout (67 MB)
__device__ float    g_x[2][ROWS];              // ping-pong iterate
__device__ float    g_bsum[2][NBLOCKS];
__device__ unsigned g_arrive = 0;
__device__ unsigned g_gen    = 0;

__device__ __forceinline__ void grid_barrier() {
    __syncthreads();
    if (threadIdx.x == 0) {
        volatile unsigned* genp = &g_gen;
        unsigned my = *genp;
        __threadfence();
        unsigned prev = atomicAdd(&g_arrive, 1u);
        if (prev == NBLOCKS - 1) {
            atomicExch(&g_arrive, 0u);
            __threadfence();
            atomicAdd(&g_gen, 1u);
        } else {
            while (*genp == my) { }
        }
        __threadfence();
    }
    __syncthreads();
}

__device__ __forceinline__ void mma16816(float& c0, float& c1, float& c2, float& c3,
                                         uint4 a, unsigned b0, unsigned b1) {
    asm volatile(
        "mma.sync.aligned.m16n8k16.row.col.f32.f16.f16.f32 "
        "{%0,%1,%2,%3}, {%4,%5,%6,%7}, {%8,%9}, {%0,%1,%2,%3};\n"
        : "+f"(c0), "+f"(c1), "+f"(c2), "+f"(c3)
        : "r"(a.x), "r"(a.y), "r"(a.z), "r"(a.w), "r"(b0), "r"(b1));
}

__global__ void __launch_bounds__(NTHREADS, 1)
fp_kernel(const float* __restrict__ A, const float* __restrict__ b,
          float* __restrict__ out)
{
    __shared__ unsigned xh2u[NN / 2];        // block's head x as half2 (4 KB)
    __shared__ float spart[8][4][16];        // row-group x kq x 16-row partials
    __shared__ float red[NWARPS];
    __shared__ float parts[NBLOCKS];

    const int tid  = threadIdx.x;
    const int warp = tid >> 5;
    const int lane = tid & 31;
    const int bid  = blockIdx.x;
    const int g    = warp >> 2;              // row-group 0..7 (16 rows each)
    const int kq   = warp & 3;               // k-quarter 0..3 (512 K each)
    const int h    = bid >> 4;               // head of this block's 128 rows
    const int l4   = lane & 3;

    int finalbuf = 0;

    for (int k = 0; k < MAX_ITER; ++k) {
        const int par = k & 1;
        float lsum = 0.f;

        if (k == 0) {
            // ---- fused: A(fp32) -> fragment-layout fp16, and x1 = tanh(b) ----
            for (size_t i = (size_t)bid * NTHREADS + tid; i < NFRAG;
                 i += (size_t)NBLOCKS * NTHREADS) {
                int ln   = (int)(i & 31);
                size_t t = i >> 5;
                int rb = (int)(t >> 7);              // row-tile 0..1023
                int kb = (int)(t & 127);             // k-tile   0..127
                int r  = rb * 16 + (ln >> 2);
                int c  = kb * 16 + (ln & 3) * 2;
                const float* Ar0 = A + (size_t)r * NN + c;
                const float* Ar8 = Ar0 + (size_t)8 * NN;
                float2 f0 = *reinterpret_cast<const float2*>(Ar0);      // (r,   c..c+1)
                float2 f1 = *reinterpret_cast<const float2*>(Ar8);      // (r+8, c..c+1)
                float2 f2 = *reinterpret_cast<const float2*>(Ar0 + 8);  // (r,   c+8..9)
                float2 f3 = *reinterpret_cast<const float2*>(Ar8 + 8);  // (r+8, c+8..9)
                __half2 q0 = __floats2half2_rn(f0.x, f0.y);
                __half2 q1 = __floats2half2_rn(f1.x, f1.y);
                __half2 q2 = __floats2half2_rn(f2.x, f2.y);
                __half2 q3 = __floats2half2_rn(f3.x, f3.y);
                uint4 u;
                u.x = *reinterpret_cast<unsigned*>(&q0);   // a0
                u.y = *reinterpret_cast<unsigned*>(&q1);   // a1
                u.z = *reinterpret_cast<unsigned*>(&q2);   // a2
                u.w = *reinterpret_cast<unsigned*>(&q3);   // a3
                g_Ahf[i] = u;
            }
            int gi = bid * NTHREADS + tid;
            if (gi < ROWS) {
                float y = tanhf(b[gi]);          // gamma*A@0 + b = b
                g_x[0][gi] = y;
                lsum = y * y;                    // diff vs x_0 = 0
            }
        } else {
            // ---- HMMA matvec: warp = 16 rows (group g) x 512 K (quarter kq) ----
            const int rb = bid * 8 + g;                       // this warp's row-tile
            const uint4* __restrict__ Af =
                g_Ahf + ((size_t)rb * KB_TILES + kq * 32) * 32 + lane;
            float c0 = 0.f, c1 = 0.f, c2 = 0.f, c3 = 0.f;
            #pragma unroll 8
            for (int t = 0; t < 32; ++t) {
                uint4 a = Af[(size_t)t * 32];
                int kb8 = (kq * 32 + t) * 8;
                unsigned b0 = xh2u[kb8 + l4];         // x pairs (2l4, 2l4+1)
                unsigned b1 = xh2u[kb8 + 4 + l4];     // x pairs (+8)
                mma16816(c0, c1, c2, c3, a, b0, b1);  // all 8 B-cols = x (broadcast)
            }
            // col 0 of D lives in lanes with lane%4==0: c0 -> row lane/4, c2 -> +8
            if (l4 == 0) {
                spart[g][kq][lane >> 2]       = c0;
                spart[g][kq][(lane >> 2) + 8] = c2;
            }
            __syncthreads();
            // combine the 4 K-partials; warps 0-7 each finish 16 rows
            if (warp < 8 && lane < 16) {
                float s = spart[warp][0][lane] + spart[warp][1][lane]
                        + spart[warp][2][lane] + spart[warp][3][lane];
                int grow = bid * 128 + warp * 16 + lane;
                float y = tanhf(GAMMA * s + b[grow]);
                float old = g_x[par ^ 1][grow];
                g_x[par][grow] = y;
                float d = old - y;
                lsum = d * d;
            }
            __syncthreads();
        }

        // ---- deterministic block reduction of lsum ----
        #pragma unroll
        for (int o = 16; o > 0; o >>= 1)
            lsum += __shfl_xor_sync(0xFFFFFFFFu, lsum, o);
        if (lane == 0) red[warp] = lsum;
        __syncthreads();
        if (warp == 0) {
            float s = red[lane];
            #pragma unroll
            for (int o = 16; o > 0; o >>= 1)
                s += __shfl_xor_sync(0xFFFFFFFFu, s, o);
            if (lane == 0) g_bsum[par][bid] = s;
        }

        grid_barrier();   // publish x_{k+1} + block sums (+ g_Ahf after k==0)

        // ---- deterministic cross-block reduction (identical in every block) ----
        if (tid < NBLOCKS) parts[tid] = g_bsum[par][tid];
        __syncthreads();
        #pragma unroll
        for (int s = NBLOCKS / 2; s > 0; s >>= 1) {
            if (tid < s) parts[tid] += parts[tid + s];
            __syncthreads();
        }
        float sumsq = parts[0];
        __syncthreads();

        if (sumsq < TOL2) break;     // z* = x_k = g_x[finalbuf] (previous accept)

        finalbuf = par;              // accept x_{k+1}
        // reload this block's head-x into smem as half2
        {
            const float2* gx2 = reinterpret_cast<const float2*>(g_x[par] + h * NN);
            float2 f = gx2[tid];                       // tid < 1024 = NN/2
            __half2 q = __floats2half2_rn(f.x, f.y);
            xh2u[tid] = *reinterpret_cast<unsigned*>(&q);
        }
        __syncthreads();
    }
    // g_x[finalbuf] = z_star (x_k on break; x_50 if exhausted) — matches torch loop.

    // ---- final differentiable step with ORIGINAL fp32 A ----
    {
        const int sub   = lane >> 3;                 // 0..3
        const int j     = lane & 7;                  // 0..7
        const int myrow = bid * 128 + warp * 4 + sub;
        const float4* A4 = reinterpret_cast<const float4*>(A + (size_t)myrow * NN);
        const float4* x4 = reinterpret_cast<const float4*>(g_x[finalbuf] + h * NN);
        float acc0 = 0.f, acc1 = 0.f;
        #pragma unroll 4
        for (int s = 0; s < 32; ++s) {
            float4 aa = A4[s * 16 + 2 * j];
            float4 ab = A4[s * 16 + 2 * j + 1];
            float4 xa = x4[s * 16 + 2 * j];
            float4 xb = x4[s * 16 + 2 * j + 1];
            acc0 = fmaf(aa.x, xa.x, acc0);
            acc0 = fmaf(aa.y, xa.y, acc0);
            acc0 = fmaf(aa.z, xa.z, acc0);
            acc0 = fmaf(aa.w, xa.w, acc0);
            acc1 = fmaf(ab.x, xb.x, acc1);
            acc1 = fmaf(ab.y, xb.y, acc1);
            acc1 = fmaf(ab.z, xb.z, acc1);
            acc1 = fmaf(ab.w, xb.w, acc1);
        }
        float acc = acc0 + acc1;
        acc += __shfl_xor_sync(0xFFFFFFFFu, acc, 1);
        acc += __shfl_xor_sync(0xFFFFFFFFu, acc, 2);
        acc += __shfl_xor_sync(0xFFFFFFFFu, acc, 4);
        if (j == 0)
            out[myrow] = tanhf(GAMMA * acc + b[myrow]);
    }
}

extern "C" void kernel_launch(void* const* d_in, const int* in_sizes, int n_in,
                              void* d_out, int out_size)
{
    const float* A = (const float*)d_in[0];
    const float* b = (const float*)d_in[1];
    if (n_in >= 2 && in_sizes[0] == ROWS) {   // defensive: A is the 33.5M-elem input
        A = (const float*)d_in[1];
        b = (const float*)d_in[0];
    }
    fp_kernel<<<NBLOCKS, NTHREADS>>>(A, b, (float*)d_out);
}